// round 8
// baseline (speedup 1.0000x reference)
#include <cuda_runtime.h>
#include <cuda_fp16.h>

typedef unsigned int u32;

#define NCONV 8
#define HO 62
#define WO 62
#define PX 48              // bytes per pixel in feature smem (32 data + 16 pad -> conflict-free ldmatrix)

__device__ __forceinline__ u32 smem_u32(const void* p) {
    u32 a;
    asm("{ .reg .u64 t; cvta.to.shared.u64 t, %1; cvt.u32.u64 %0, t; }" : "=r"(a) : "l"(p));
    return a;
}
// pack two f32 -> f16x2 (lo arg in low half)
__device__ __forceinline__ u32 pack_h2(float lo, float hi) {
    u32 r; asm("cvt.rn.f16x2.f32 %0, %1, %2;" : "=r"(r) : "f"(hi), "f"(lo)); return r;
}
__device__ __forceinline__ void ldsm_x4(u32 &r0, u32 &r1, u32 &r2, u32 &r3, u32 addr) {
    asm volatile("ldmatrix.sync.aligned.m8n8.x4.shared.b16 {%0,%1,%2,%3}, [%4];"
                 : "=r"(r0), "=r"(r1), "=r"(r2), "=r"(r3) : "r"(addr));
}
__device__ __forceinline__ void mma_k16(float c[4], u32 a0, u32 a1, u32 a2, u32 a3,
                                        u32 b0, u32 b1) {
    asm volatile(
        "mma.sync.aligned.m16n8k16.row.col.f32.f16.f16.f32 "
        "{%0,%1,%2,%3}, {%4,%5,%6,%7}, {%8,%9}, {%0,%1,%2,%3};"
        : "+f"(c[0]), "+f"(c[1]), "+f"(c[2]), "+f"(c[3])
        : "r"(a0), "r"(a1), "r"(a2), "r"(a3), "r"(b0), "r"(b1));
}

__global__ __launch_bounds__(256, 4)
void kan_hmma2(const float* __restrict__ x,
               const float* __restrict__ base_w,
               const float* __restrict__ spline_w,
               const float* __restrict__ spline_s,
               const float* __restrict__ grid,
               float* __restrict__ out) {
    // feature plane: 10 input rows x 64 cols (+2 overread pad), PX bytes per pixel
    __shared__ __align__(16) char   s_feat[642 * PX];        // 30816 B
    __shared__ __align__(16) __half s_bt[9 * 8 * 16];        // [tap][n][k]  2304 B

    const int tid  = threadIdx.x;
    const int w    = tid >> 5;
    const int lane = tid & 31;
    const int band = blockIdx.x;     // 0..7  (8 output rows each; band 7 has 6)
    const int img  = blockIdx.y;     // 0..255

    // ---- B staging: Bt[tap][n][k] fp16 ----
    // k=0: bw_hi | k=1..8: scaled spline | k=9: bw_hi | k=10: bw_lo | k>=11: 0
    for (int idx = tid; idx < 9 * 8 * 16; idx += 256) {
        int tap = idx >> 7, rem = idx & 127, n = rem >> 4, k = rem & 15;
        __half hv = __float2half_rn(0.0f);
        if (k == 0 || k == 9) {
            hv = __float2half_rn(base_w[n * 9 + tap]);
        } else if (k <= 8) {
            hv = __float2half_rn(spline_w[(n * 9 + tap) * NCONV + (k - 1)]
                                 * spline_s[n * 9 + tap]);
        } else if (k == 10) {
            float bw = base_w[n * 9 + tap];
            hv = __float2half_rn(bw - __half2float(__float2half_rn(bw)));
        }
        s_bt[idx] = hv;
    }

    const float g0    = grid[0];
    const float inv_h = 1.0f / (grid[1] - grid[0]);
    __syncthreads();

    // ---- hoist B fragments (k16, col layout): b0 = Bt[tap][lane/4][2*(lane%4)], b1 = +8 ----
    u32 bf0[9], bf1[9];
    #pragma unroll
    for (int tap = 0; tap < 9; ++tap) {
        const __half* r = s_bt + tap * 128 + (lane >> 2) * 16 + 2 * (lane & 3);
        bf0[tap] = *(const u32*)r;
        bf1[tap] = *(const u32*)(r + 8);
    }

    // ---- A-build: 10 input rows x 64 cols, 16-half feature vector per pixel ----
    const float* xin = x + img * 4096;
    for (int e = tid; e < 640; e += 256) {
        int irow = e >> 6, col = e & 63;
        int yin  = band * 8 + irow;
        if (yin > 63) yin = 63;                 // band 7 clamp (rows masked at store)
        float v = xin[yin * 64 + col];

        float sig  = 1.0f / (1.0f + __expf(-v));
        float silu = v * sig;
        float slo  = silu - __half2float(__float2half_rn(silu));   // fp16 residual

        float u  = (v - g0) * inv_h;
        float fj = floorf(u);
        int   j0 = (int)fj;
        float tt = u - fj;
        float t2 = tt * tt, t3 = t2 * tt, om = 1.0f - tt;
        const float s6 = 1.0f / 6.0f;
        float c0 = om * om * om * s6;
        float c1 = (3.0f * t3 - 6.0f * t2 + 4.0f) * s6;
        float c2 = (-3.0f * t3 + 3.0f * t2 + 3.0f * tt + 1.0f) * s6;
        float c3 = t3 * s6;
        int jb = j0 - 3;                        // basis index holding c0

        float bas[8];
        #pragma unroll
        for (int j = 0; j < 8; ++j) {
            int d = j - jb;
            bas[j] = (d == 0) ? c0 : (d == 1) ? c1 : (d == 2) ? c2 : (d == 3) ? c3 : 0.0f;
        }

        char* bp = s_feat + e * PX;
        *(uint4*)bp = make_uint4(pack_h2(silu,   bas[0]),
                                 pack_h2(bas[1], bas[2]),
                                 pack_h2(bas[3], bas[4]),
                                 pack_h2(bas[5], bas[6]));
        *(uint4*)(bp + 16) = make_uint4(pack_h2(bas[7], slo),
                                        pack_h2(silu, 0.0f), 0u, 0u);
    }
    __syncthreads();

    // ---- tensor phase: warp w = output row band*8+w; 4 m16 tiles (64 px) per warp ----
    const u32 fb = smem_u32(s_feat);
    u32 abase[4];
    #pragma unroll
    for (int tau = 0; tau < 4; ++tau)
        abase[tau] = fb + (u32)((w * 64 + tau * 16 + (lane & 15)) * PX)
                        + (u32)((lane >> 4) * 16);

    float c[4][4];
    #pragma unroll
    for (int tau = 0; tau < 4; ++tau)
        #pragma unroll
        for (int i = 0; i < 4; ++i) c[tau][i] = 0.0f;

    #pragma unroll
    for (int tap = 0; tap < 9; ++tap) {
        const int dy = tap / 3, dx = tap % 3;
        const u32 off = (u32)((dy * 64 + dx) * PX);
        #pragma unroll
        for (int tau = 0; tau < 4; ++tau) {
            u32 a0, a1, a2, a3;
            ldsm_x4(a0, a1, a2, a3, abase[tau] + off);
            mma_k16(c[tau], a0, a1, a2, a3, bf0[tap], bf1[tap]);
        }
    }

    // ---- store: c-frag rows = output cols, frag cols = conv index ----
    const int y = band * 8 + w;
    if (y < HO) {
        const int n0 = 2 * (lane & 3);
        float* p0 = out + ((img * NCONV + n0) * HO + y) * WO;
        float* p1 = p0 + HO * WO;
        #pragma unroll
        for (int tau = 0; tau < 4; ++tau) {
            #pragma unroll
            for (int g = 0; g < 2; ++g) {
                int xo = tau * 16 + g * 8 + (lane >> 2);
                if (xo < WO) {
                    p0[xo] = c[tau][g * 2 + 0];
                    p1[xo] = c[tau][g * 2 + 1];
                }
            }
        }
    }
}

extern "C" void kernel_launch(void* const* d_in, const int* in_sizes, int n_in,
                              void* d_out, int out_size) {
    const float* x  = (const float*)d_in[0];
    const float* bw = (const float*)d_in[1];
    const float* sw = (const float*)d_in[2];
    const float* ss = (const float*)d_in[3];
    const float* gr = (const float*)d_in[4];
    float* out = (float*)d_out;

    dim3 grd(8, 256);   // 8 row-bands x 256 images
    kan_hmma2<<<grd, 256>>>(x, bw, sw, ss, gr, out);
}